// round 15
// baseline (speedup 1.0000x reference)
#include <cuda_runtime.h>
#include <cuda_fp16.h>
#include <math.h>
#include <stdint.h>

// ---------------- problem constants ----------------
constexpr int T    = 2048;
constexpr int HID  = 4096;
constexpr int NH   = 32;
constexpr int DQ   = 256;
constexpr int DN   = 192;
constexpr int DR   = 64;
constexpr int DV   = 256;
constexpr int DKV  = 512;
constexpr int QLORA= 2048;
constexpr int HDQ  = NH * DQ;        // 8192
constexpr int KVW  = NH * (DN + DV); // 14336
constexpr int LATW = DKV + DR;       // 576
constexpr int DPW  = QLORA + LATW;   // 2624

// ---------------- buffers ----------------
__device__ float  g_dp_part [4][(size_t)T * DPW];   // down-proj split-K=4 partials
__device__ float  g_out_part[4][(size_t)T * HID];   // wo split-K=4 partials
__device__ __half g_hid_f  [(size_t)T * HID];
__device__ __half g_qlo_f  [(size_t)T * QLORA];
__device__ __half g_lat_f  [(size_t)T * DKV];
__device__ __half g_kpe    [(size_t)T * DR];
__device__ __half g_qf     [(size_t)T * HDQ];       // q, pre-scaled by 1/16
__device__ __half g_kv16   [(size_t)T * KVW];
__device__ __half g_Of     [(size_t)T * HDQ];
__device__ __half g_Kc_f   [(size_t)T * HDQ];
__device__ __half g_Vt_f   [(size_t)NH * DV * T];
__device__ __half g_wdTf   [(size_t)DPW * HID];
__device__ __half g_wqbTf  [(size_t)HDQ * QLORA];
__device__ __half g_wkvbTf [(size_t)KVW * DKV];
__device__ __half g_woTf   [(size_t)HID * HDQ];

// ---------------- helpers ----------------
__device__ __forceinline__ void mma_f16(float* c, const uint32_t* a, const uint32_t* b) {
    asm volatile(
        "mma.sync.aligned.m16n8k16.row.col.f32.f16.f16.f32 "
        "{%0,%1,%2,%3}, {%4,%5,%6,%7}, {%8,%9}, {%0,%1,%2,%3};\n"
        : "+f"(c[0]), "+f"(c[1]), "+f"(c[2]), "+f"(c[3])
        : "r"(a[0]), "r"(a[1]), "r"(a[2]), "r"(a[3]), "r"(b[0]), "r"(b[1]));
}

__device__ __forceinline__ void ldsm4(uint32_t& r0, uint32_t& r1, uint32_t& r2, uint32_t& r3, uint32_t a) {
    asm volatile("ldmatrix.sync.aligned.m8n8.x4.shared.b16 {%0,%1,%2,%3}, [%4];"
        : "=r"(r0), "=r"(r1), "=r"(r2), "=r"(r3) : "r"(a));
}

__device__ __forceinline__ void cp16(uint32_t d, const void* s) {
    asm volatile("cp.async.cg.shared.global [%0], [%1], 16;" :: "r"(d), "l"(s));
}

constexpr int F_TILE  = 128 * 80;
constexpr int P_STAGE = 2 * F_TILE;
constexpr int SMEM_1P = 2 * P_STAGE;     // 40960

// ============================================================================
// 1-pass fp16 GEMM with optional split-K (blockIdx.z = k-slice).
// ============================================================================
template <typename OutT>
__global__ __launch_bounds__(256, 2) void tgemm_1p(
    const __half* __restrict__ Ah, const __half* __restrict__ Bh,
    OutT* __restrict__ C,
    int M, int N, int K, int lda, int ldb, int ldc, long sC)
{
    const int bx = blockIdx.x, by = blockIdx.y;
    Ah += (long)blockIdx.z * K;
    Bh += (long)blockIdx.z * K;
    C  += (long)blockIdx.z * sC;

    extern __shared__ char smem[];
    const uint32_t sb = (uint32_t)__cvta_generic_to_shared(smem);

    const int tid = threadIdx.x, lane = tid & 31, warp = tid >> 5;
    const int wm = warp & 1, wn = warp >> 1;
    const int g = lane >> 2, t4 = lane & 3;
    const int r0 = tid >> 2, c4 = tid & 3;
    const int Nm1 = N - 1;

    const int lr  = (lane & 7) + ((lane >> 3) & 1) * 8;
    const int lkb = (lane >> 4) * 16;
    const uint32_t aBase = sb + (uint32_t)((wm * 64 + lr) * 80 + lkb);
    const uint32_t bBase = sb + (uint32_t)(F_TILE + (wn * 32 + lr) * 80 + lkb);

    float acc[4][4][4] = {};
    const int nchunks = K / 32;

    auto load_chunk = [&](int k0, uint32_t st) {
        #pragma unroll
        for (int c = 0; c < 2; c++) {
            int row = r0 + c * 64;
            uint32_t ds = sb + st + (uint32_t)(row * 80 + c4 * 16);
            long aoff = (long)(by * 128 + row) * lda + k0 + c4 * 8;
            cp16(ds, Ah + aoff);
            int nr = bx * 128 + row; if (nr > Nm1) nr = Nm1;
            long boff = (long)nr * ldb + k0 + c4 * 8;
            cp16(ds + F_TILE, Bh + boff);
        }
    };

    load_chunk(0, 0);
    asm volatile("cp.async.commit_group;");

    for (int i = 0; i < nchunks; i++) {
        if (i + 1 < nchunks)
            load_chunk((i + 1) * 32, (uint32_t)(((i + 1) & 1) * P_STAGE));
        asm volatile("cp.async.commit_group;");
        asm volatile("cp.async.wait_group 1;");
        __syncthreads();

        const uint32_t sof = (uint32_t)((i & 1) * P_STAGE);
        #pragma unroll
        for (int ks = 0; ks < 2; ks++) {
            uint32_t bh[4][2];
            #pragma unroll
            for (int p = 0; p < 2; p++) {
                uint32_t ad = bBase + sof + (uint32_t)(p * 16 * 80 + ks * 32);
                uint32_t x0, x1, x2, x3;
                ldsm4(x0, x1, x2, x3, ad);
                bh[2*p][0] = x0; bh[2*p+1][0] = x1; bh[2*p][1] = x2; bh[2*p+1][1] = x3;
            }
            #pragma unroll
            for (int mt = 0; mt < 4; mt++) {
                uint32_t ah[4];
                uint32_t ad = aBase + sof + (uint32_t)(mt * 16 * 80 + ks * 32);
                ldsm4(ah[0], ah[1], ah[2], ah[3], ad);
                #pragma unroll
                for (int nt = 0; nt < 4; nt++)
                    mma_f16(acc[mt][nt], ah, bh[nt]);
            }
        }
        __syncthreads();
    }

    #pragma unroll
    for (int mt = 0; mt < 4; mt++) {
        int r = by * 128 + wm * 64 + mt * 16 + g;
        #pragma unroll
        for (int nt = 0; nt < 4; nt++) {
            int c = bx * 128 + wn * 32 + nt * 8 + 2 * t4;
            if (c < N) {
                if (sizeof(OutT) == 4) {
                    float* Cf = (float*)C;
                    *(float2*)&Cf[(long)r * ldc + c]       = make_float2(acc[mt][nt][0], acc[mt][nt][1]);
                    *(float2*)&Cf[(long)(r + 8) * ldc + c] = make_float2(acc[mt][nt][2], acc[mt][nt][3]);
                } else {
                    __half* Ch = (__half*)C;
                    *(__half2*)&Ch[(long)r * ldc + c]       = __floats2half2_rn(acc[mt][nt][0], acc[mt][nt][1]);
                    *(__half2*)&Ch[(long)(r + 8) * ldc + c] = __floats2half2_rn(acc[mt][nt][2], acc[mt][nt][3]);
                }
            }
        }
    }
}

// ============================================================================
// Dual up-projection: bx<64 -> qf = (qlo @ wqb^T) * 1/16 ; else kv16 = lat @ wkvb^T.
// Single tile pool so work-stealing fills partial waves.
// ============================================================================
__global__ __launch_bounds__(256, 2) void up_proj_k(
    const __half* __restrict__ qlo, const __half* __restrict__ wqb, __half* __restrict__ qOut,
    const __half* __restrict__ lat, const __half* __restrict__ wkvb, __half* __restrict__ kvOut)
{
    const int bxr = blockIdx.x, by = blockIdx.y;
    const __half *Ah, *Bh;
    __half* C;
    int N, K, lda, ldb, ldc, bx;
    float oscale;
    if (bxr < 64) {
        Ah = qlo; Bh = wqb; C = qOut;
        N = HDQ; K = QLORA; lda = QLORA; ldb = QLORA; ldc = HDQ;
        bx = bxr; oscale = 0.0625f;
    } else {
        Ah = lat; Bh = wkvb; C = kvOut;
        N = KVW; K = DKV; lda = DKV; ldb = DKV; ldc = KVW;
        bx = bxr - 64; oscale = 1.f;
    }

    extern __shared__ char smem[];
    const uint32_t sb = (uint32_t)__cvta_generic_to_shared(smem);

    const int tid = threadIdx.x, lane = tid & 31, warp = tid >> 5;
    const int wm = warp & 1, wn = warp >> 1;
    const int g = lane >> 2, t4 = lane & 3;
    const int r0 = tid >> 2, c4 = tid & 3;
    const int Nm1 = N - 1;

    const int lr  = (lane & 7) + ((lane >> 3) & 1) * 8;
    const int lkb = (lane >> 4) * 16;
    const uint32_t aBase = sb + (uint32_t)((wm * 64 + lr) * 80 + lkb);
    const uint32_t bBase = sb + (uint32_t)(F_TILE + (wn * 32 + lr) * 80 + lkb);

    float acc[4][4][4] = {};
    const int nchunks = K / 32;

    auto load_chunk = [&](int k0, uint32_t st) {
        #pragma unroll
        for (int c = 0; c < 2; c++) {
            int row = r0 + c * 64;
            uint32_t ds = sb + st + (uint32_t)(row * 80 + c4 * 16);
            long aoff = (long)(by * 128 + row) * lda + k0 + c4 * 8;
            cp16(ds, Ah + aoff);
            int nr = bx * 128 + row; if (nr > Nm1) nr = Nm1;
            long boff = (long)nr * ldb + k0 + c4 * 8;
            cp16(ds + F_TILE, Bh + boff);
        }
    };

    load_chunk(0, 0);
    asm volatile("cp.async.commit_group;");

    for (int i = 0; i < nchunks; i++) {
        if (i + 1 < nchunks)
            load_chunk((i + 1) * 32, (uint32_t)(((i + 1) & 1) * P_STAGE));
        asm volatile("cp.async.commit_group;");
        asm volatile("cp.async.wait_group 1;");
        __syncthreads();

        const uint32_t sof = (uint32_t)((i & 1) * P_STAGE);
        #pragma unroll
        for (int ks = 0; ks < 2; ks++) {
            uint32_t bh[4][2];
            #pragma unroll
            for (int p = 0; p < 2; p++) {
                uint32_t ad = bBase + sof + (uint32_t)(p * 16 * 80 + ks * 32);
                uint32_t x0, x1, x2, x3;
                ldsm4(x0, x1, x2, x3, ad);
                bh[2*p][0] = x0; bh[2*p+1][0] = x1; bh[2*p][1] = x2; bh[2*p+1][1] = x3;
            }
            #pragma unroll
            for (int mt = 0; mt < 4; mt++) {
                uint32_t ah[4];
                uint32_t ad = aBase + sof + (uint32_t)(mt * 16 * 80 + ks * 32);
                ldsm4(ah[0], ah[1], ah[2], ah[3], ad);
                #pragma unroll
                for (int nt = 0; nt < 4; nt++)
                    mma_f16(acc[mt][nt], ah, bh[nt]);
            }
        }
        __syncthreads();
    }

    #pragma unroll
    for (int mt = 0; mt < 4; mt++) {
        int r = by * 128 + wm * 64 + mt * 16 + g;
        #pragma unroll
        for (int nt = 0; nt < 4; nt++) {
            int c = bx * 128 + wn * 32 + nt * 8 + 2 * t4;
            if (c < N) {
                *(__half2*)&C[(long)r * ldc + c] =
                    __floats2half2_rn(acc[mt][nt][0] * oscale, acc[mt][nt][1] * oscale);
                *(__half2*)&C[(long)(r + 8) * ldc + c] =
                    __floats2half2_rn(acc[mt][nt][2] * oscale, acc[mt][nt][3] * oscale);
            }
        }
    }
}

// ============================================================================
// Fused flash attention, fp16 1-term, Q smem-resident, Q pre-scaled.
// ============================================================================
constexpr int QPL  = 10240;
constexpr int KOFF = 8 * QPL;
constexpr int VPL  = 34816;
constexpr int VOFF = KOFF + 2 * QPL;
constexpr int FA_SMEM = VOFF + 2 * VPL;  // 172032

__global__ __launch_bounds__(256, 1) void flash_k(
    const __half* __restrict__ Qf, const __half* __restrict__ Kf,
    const __half* __restrict__ Vf, __half* __restrict__ Of)
{
    const int qi = gridDim.x - 1 - blockIdx.x;
    const int h  = blockIdx.y;

    extern __shared__ char smem[];
    const uint32_t sb = (uint32_t)__cvta_generic_to_shared(smem);

    const int tid = threadIdx.x, lane = tid & 31, w = tid >> 5;
    const int g = lane >> 2, t4 = lane & 3;
    const int lr  = (lane & 7) + ((lane >> 3) & 1) * 8;
    const int lkb = (lane >> 4) * 16;

    #pragma unroll
    for (int p = 0; p < 16; p++) {
        int id = tid + p * 256;
        int chunk = id >> 9, wi = id & 511;
        int row = wi >> 2, cc = wi & 3;
        uint32_t dst = sb + (uint32_t)(chunk * QPL + row * 80 + cc * 16);
        size_t qo = (size_t)(qi * 128 + row) * HDQ + h * DQ + chunk * 32 + cc * 8;
        cp16(dst, Qf + qo);
    }
    asm volatile("cp.async.commit_group;");

    float oacc[32][4];
    #pragma unroll
    for (int i = 0; i < 32; i++)
        #pragma unroll
        for (int c = 0; c < 4; c++) oacc[i][c] = 0.f;
    float m0 = -1e30f, m1 = -1e30f, l0 = 0.f, l1 = 0.f;

    for (int j = 0; j <= qi; j++) {
        float sacc[16][4] = {};

        auto load_kc = [&](int i, uint32_t st) {
            const int d = i * 32;
            #pragma unroll
            for (int p = 0; p < 2; p++) {
                int id = tid + p * 256;
                int row = id >> 2, cc = id & 3;
                uint32_t dst = sb + st + (uint32_t)(row * 80 + cc * 16);
                size_t ko = (size_t)(j * 128 + row) * HDQ + h * DQ + d + cc * 8;
                cp16(dst, Kf + ko);
            }
        };

        load_kc(0, KOFF);
        asm volatile("cp.async.commit_group;");
        load_kc(1, KOFF + QPL);
        asm volatile("cp.async.commit_group;");

        #pragma unroll
        for (int dvc = 0; dvc < 2; dvc++) {
            #pragma unroll
            for (int p = 0; p < 4; p++) {
                int id = tid + p * 256;
                int row = id >> 3, cc = id & 7;
                uint32_t dst = sb + (uint32_t)(VOFF + dvc * VPL + row * 272 + cc * 32);
                size_t vo = (size_t)h * DV * T + (size_t)(dvc * 128 + row) * T + j * 128 + cc * 16;
                cp16(dst,      Vf + vo);
                cp16(dst + 16, Vf + vo + 8);
            }
        }
        asm volatile("cp.async.commit_group;");

        for (int i = 0; i < 8; i++) {
            asm volatile("cp.async.wait_group 1;");
            __syncthreads();
            const uint32_t st = (uint32_t)(KOFF + (i & 1) * QPL);
            const uint32_t qBase = sb + (uint32_t)(i * QPL + (w * 16 + lr) * 80 + lkb);
            #pragma unroll
            for (int ks = 0; ks < 2; ks++) {
                uint32_t ah[4];
                ldsm4(ah[0], ah[1], ah[2], ah[3], qBase + ks * 32);
                #pragma unroll
                for (int p = 0; p < 8; p++) {
                    uint32_t bh[2][2], x0, x1, x2, x3;
                    uint32_t bd = sb + st + (uint32_t)((p * 16 + lr) * 80 + lkb + ks * 32);
                    ldsm4(x0, x1, x2, x3, bd);
                    bh[0][0] = x0; bh[1][0] = x1; bh[0][1] = x2; bh[1][1] = x3;
                    #pragma unroll
                    for (int q2 = 0; q2 < 2; q2++)
                        mma_f16(sacc[p * 2 + q2], ah, bh[q2]);
                }
            }
            __syncthreads();
            if (i + 2 < 8) load_kc(i + 2, st);
            asm volatile("cp.async.commit_group;");
        }
        asm volatile("cp.async.wait_group 0;");

        // ---------------- softmax (Q pre-scaled; no scale pass) ----------------
        if (j == qi) {
            const int rr0 = w * 16 + g, rr1 = rr0 + 8;
            #pragma unroll
            for (int nt = 0; nt < 16; nt++) {
                int col = nt * 8 + 2 * t4;
                if (col     > rr0) sacc[nt][0] = -1e30f;
                if (col + 1 > rr0) sacc[nt][1] = -1e30f;
                if (col     > rr1) sacc[nt][2] = -1e30f;
                if (col + 1 > rr1) sacc[nt][3] = -1e30f;
            }
        }

        float tm0 = -1e30f, tm1 = -1e30f;
        #pragma unroll
        for (int nt = 0; nt < 16; nt++) {
            tm0 = fmaxf(tm0, fmaxf(sacc[nt][0], sacc[nt][1]));
            tm1 = fmaxf(tm1, fmaxf(sacc[nt][2], sacc[nt][3]));
        }
        tm0 = fmaxf(tm0, __shfl_xor_sync(0xffffffffu, tm0, 1));
        tm0 = fmaxf(tm0, __shfl_xor_sync(0xffffffffu, tm0, 2));
        tm1 = fmaxf(tm1, __shfl_xor_sync(0xffffffffu, tm1, 1));
        tm1 = fmaxf(tm1, __shfl_xor_sync(0xffffffffu, tm1, 2));

        float nm0 = fmaxf(m0, tm0), nm1 = fmaxf(m1, tm1);
        float a0 = expf(m0 - nm0), a1 = expf(m1 - nm1);
        m0 = nm0; m1 = nm1;

        float s0 = 0.f, s1 = 0.f;
        #pragma unroll
        for (int nt = 0; nt < 16; nt++) {
            sacc[nt][0] = expf(sacc[nt][0] - m0); s0 += sacc[nt][0];
            sacc[nt][1] = expf(sacc[nt][1] - m0); s0 += sacc[nt][1];
            sacc[nt][2] = expf(sacc[nt][2] - m1); s1 += sacc[nt][2];
            sacc[nt][3] = expf(sacc[nt][3] - m1); s1 += sacc[nt][3];
        }
        s0 += __shfl_xor_sync(0xffffffffu, s0, 1);
        s0 += __shfl_xor_sync(0xffffffffu, s0, 2);
        s1 += __shfl_xor_sync(0xffffffffu, s1, 1);
        s1 += __shfl_xor_sync(0xffffffffu, s1, 2);
        l0 = l0 * a0 + s0;
        l1 = l1 * a1 + s1;

        #pragma unroll
        for (int i = 0; i < 32; i++) {
            oacc[i][0] *= a0; oacc[i][1] *= a0;
            oacc[i][2] *= a1; oacc[i][3] *= a1;
        }

        uint32_t Pf[8][4];
        #pragma unroll
        for (int ks = 0; ks < 8; ks++) {
            #pragma unroll
            for (int hf = 0; hf < 2; hf++) {
                const float* c = sacc[2 * ks + hf];
                __half2 v01 = __floats2half2_rn(c[0], c[1]);
                __half2 v23 = __floats2half2_rn(c[2], c[3]);
                Pf[ks][hf * 2]     = *(uint32_t*)&v01;
                Pf[ks][hf * 2 + 1] = *(uint32_t*)&v23;
            }
        }

        __syncthreads();
        #pragma unroll
        for (int dvc = 0; dvc < 2; dvc++) {
            #pragma unroll
            for (int ks = 0; ks < 8; ks++) {
                #pragma unroll
                for (int p = 0; p < 8; p++) {
                    uint32_t vh[2][2], x0, x1, x2, x3;
                    uint32_t bd = sb + (uint32_t)(VOFF + dvc * VPL + (p * 16 + lr) * 272 + lkb + ks * 32);
                    ldsm4(x0, x1, x2, x3, bd);
                    vh[0][0] = x0; vh[1][0] = x1; vh[0][1] = x2; vh[1][1] = x3;
                    #pragma unroll
                    for (int q2 = 0; q2 < 2; q2++)
                        mma_f16(oacc[dvc * 16 + p * 2 + q2], Pf[ks], vh[q2]);
                }
            }
        }
        __syncthreads();
    }

    const float i0 = 1.f / l0, i1 = 1.f / l1;
    const int r0 = qi * 128 + w * 16 + g;
    __half* o0 = Of + (size_t)r0 * HDQ + h * DV;
    __half* o1 = o0 + (size_t)8 * HDQ;
    #pragma unroll
    for (int nt = 0; nt < 32; nt++) {
        int c = nt * 8 + 2 * t4;
        __half2 v0 = __floats2half2_rn(oacc[nt][0] * i0, oacc[nt][1] * i0);
        __half2 v1 = __floats2half2_rn(oacc[nt][2] * i1, oacc[nt][3] * i1);
        *(__half2*)&o0[c] = v0;
        *(__half2*)&o1[c] = v1;
    }
}

// ---------------- fp32 -> fp16 ----------------
__global__ void conv_f16_k(const float* __restrict__ x, __half* __restrict__ h, long n)
{
    long i = (long)blockIdx.x * blockDim.x + threadIdx.x;
    long stride = (long)gridDim.x * blockDim.x;
    for (; i < n; i += stride) h[i] = __float2half_rn(x[i]);
}

// ---------------- fp32 [R,C] -> fp16 transposed [C,R] ----------------
__global__ void conv_tr_f16_k(const float* __restrict__ x, __half* __restrict__ h, int R, int C)
{
    __shared__ float tile[32][33];
    const int c0 = blockIdx.x * 32, rr0 = blockIdx.y * 32;
    const int tx = threadIdx.x & 31, ty = threadIdx.x >> 5;
    #pragma unroll
    for (int i = 0; i < 4; i++) {
        int r = rr0 + ty + i * 8;
        tile[ty + i * 8][tx] = x[(long)r * C + c0 + tx];
    }
    __syncthreads();
    #pragma unroll
    for (int i = 0; i < 4; i++) {
        int c = c0 + ty + i * 8;
        long o = (long)c * R + rr0 + tx;
        h[o] = __float2half_rn(tile[tx][ty + i * 8]);
    }
}

// ---------------- RMSNorm from 4 fp32 partials -> fp16 ----------------
__global__ void rmsnorm_4p_k(const float* __restrict__ pp, long sP,
                             const float* __restrict__ w, __half* __restrict__ o,
                             int N, int ldin)
{
    long rb = (long)blockIdx.x * ldin;
    __shared__ float red[8];
    __shared__ float bc;
    const int lane = threadIdx.x & 31, wid = threadIdx.x >> 5;

    float s = 0.f;
    for (int j = threadIdx.x; j < N; j += blockDim.x) {
        float v = pp[rb + j] + pp[sP + rb + j] + pp[2 * sP + rb + j] + pp[3 * sP + rb + j];
        s += v * v;
    }
    #pragma unroll
    for (int of = 16; of; of >>= 1) s += __shfl_xor_sync(0xffffffffu, s, of);
    if (lane == 0) red[wid] = s;
    __syncthreads();
    if (threadIdx.x == 0) {
        float v = 0.f;
        for (int wI = 0; wI < 8; wI++) v += red[wI];
        bc = rsqrtf(v / N + 1e-6f);
    }
    __syncthreads();
    float r = bc;
    long ob = (long)blockIdx.x * N;
    for (int j = threadIdx.x; j < N; j += blockDim.x) {
        float v = pp[rb + j] + pp[sP + rb + j] + pp[2 * sP + rb + j] + pp[3 * sP + rb + j];
        o[ob + j] = __float2half_rn(v * r * w[j]);
    }
}

// ---------------- rope k_pe from 4 fp32 partials -> fp16 kpe ----------------
__global__ void rope_kpe_4p_k(const float* __restrict__ pp, long sP,
                              const int* __restrict__ pos, __half* __restrict__ kpe)
{
    const int tt = blockIdx.x, i = threadIdx.x;
    double inv = pow(10000.0, -(double)i / 32.0);
    double sd, cd;
    sincos((double)pos[tt] * inv, &sd, &cd);
    float c = (float)cd, s = (float)sd;
    long rb = (long)tt * DPW + QLORA + DKV;
    float x1 = pp[rb + i]      + pp[sP + rb + i]      + pp[2*sP + rb + i]      + pp[3*sP + rb + i];
    float x2 = pp[rb + i + 32] + pp[sP + rb + i + 32] + pp[2*sP + rb + i + 32] + pp[3*sP + rb + i + 32];
    kpe[(long)tt * DR + i]      = __float2half_rn(x1 * c - x2 * s);
    kpe[(long)tt * DR + i + 32] = __float2half_rn(x2 * c + x1 * s);
}

// ---------------- rope q in-place (scaled values rotate identically) ----------
__global__ void rope_q_inpl_k(__half* __restrict__ q, const int* __restrict__ pos)
{
    const int tt = blockIdx.x;
    const int i = threadIdx.x & 31, wg = threadIdx.x >> 5;
    double inv = pow(10000.0, -(double)i / 32.0);
    double sd, cd;
    sincos((double)pos[tt] * inv, &sd, &cd);
    float c = (float)cd, s = (float)sd;
    for (int h = wg; h < NH; h += 8) {
        __half* p = q + (size_t)tt * HDQ + h * DQ + DN;
        float x1 = __half2float(p[i]), x2 = __half2float(p[i + 32]);
        p[i]      = __float2half_rn(x1 * c - x2 * s);
        p[i + 32] = __float2half_rn(x2 * c + x1 * s);
    }
}

// ---------------- K assembly ----------------
__global__ void build_K_h_k(const __half* __restrict__ kv, const __half* __restrict__ kpe,
                            __half* __restrict__ Kc)
{
    const int tt = blockIdx.x;
    long ob = (long)tt * HDQ;
    for (int x = threadIdx.x; x < HDQ; x += blockDim.x) {
        int hd = x >> 8, d = x & 255;
        __half v = (d < DN) ? kv[(size_t)tt * KVW + hd * (DN + DV) + d]
                            : kpe[(long)tt * DR + (d - DN)];
        Kc[ob + x] = v;
    }
}

// ---------------- V transpose per head -> [h][DV][T] ----------------
__global__ void transpose_v_h_k(const __half* __restrict__ kv, __half* __restrict__ h)
{
    __shared__ __half tile[32][34];
    const int d0 = blockIdx.x * 32, t0 = blockIdx.y * 32, hd = blockIdx.z;
    const int tx = threadIdx.x & 31, ty = threadIdx.x >> 5;
    #pragma unroll
    for (int i = 0; i < 4; i++) {
        int tr = t0 + ty + i * 8;
        tile[ty + i * 8][tx] = kv[(size_t)tr * KVW + hd * (DN + DV) + DN + d0 + tx];
    }
    __syncthreads();
    #pragma unroll
    for (int i = 0; i < 4; i++) {
        int d = d0 + ty + i * 8;
        long o = (long)hd * DV * T + (long)d * T + t0 + tx;
        h[o] = tile[tx][ty + i * 8];
    }
}

// ---------------- 4-way fp32 reduction ----------------
__global__ void reduce4_k(const float* __restrict__ p0, const float* __restrict__ p1,
                          const float* __restrict__ p2, const float* __restrict__ p3,
                          float* __restrict__ o, long n4)
{
    long i = (long)blockIdx.x * blockDim.x + threadIdx.x;
    long stride = (long)gridDim.x * blockDim.x;
    for (; i < n4; i += stride) {
        float4 a = ((const float4*)p0)[i];
        float4 b = ((const float4*)p1)[i];
        float4 c = ((const float4*)p2)[i];
        float4 d = ((const float4*)p3)[i];
        ((float4*)o)[i] = make_float4(a.x + b.x + c.x + d.x, a.y + b.y + c.y + d.y,
                                      a.z + b.z + c.z + d.z, a.w + b.w + c.w + d.w);
    }
}

// ---------------- launch ----------------
extern "C" void kernel_launch(void* const* d_in, const int* in_sizes, int n_in,
                              void* d_out, int out_size)
{
    (void)in_sizes; (void)n_in; (void)out_size;
    const float* hidden = (const float*)d_in[0];
    const int*   pos    = (const int*)  d_in[1];
    const float* wq_a   = (const float*)d_in[2];
    const float* q_ln   = (const float*)d_in[3];
    const float* wq_b   = (const float*)d_in[4];
    const float* wkv_a  = (const float*)d_in[5];
    const float* kv_ln  = (const float*)d_in[6];
    const float* wkv_b  = (const float*)d_in[7];
    const float* wo     = (const float*)d_in[8];
    float* out = (float*)d_out;

    cudaFuncSetAttribute(tgemm_1p<__half>, cudaFuncAttributeMaxDynamicSharedMemorySize, SMEM_1P);
    cudaFuncSetAttribute(tgemm_1p<float>,  cudaFuncAttributeMaxDynamicSharedMemorySize, SMEM_1P);
    cudaFuncSetAttribute(up_proj_k,        cudaFuncAttributeMaxDynamicSharedMemorySize, SMEM_1P);
    cudaFuncSetAttribute(flash_k,          cudaFuncAttributeMaxDynamicSharedMemorySize, FA_SMEM);

    float *dpp, *outp;
    cudaGetSymbolAddress((void**)&dpp,  g_dp_part);
    cudaGetSymbolAddress((void**)&outp, g_out_part);

    __half *hidf, *qlof, *latf, *kpe, *qf, *kv16, *Ofp, *Kcf, *Vtf,
           *wdTf, *wqbTf, *wkvbTf, *woTf;
    cudaGetSymbolAddress((void**)&hidf,   g_hid_f);
    cudaGetSymbolAddress((void**)&qlof,   g_qlo_f);
    cudaGetSymbolAddress((void**)&latf,   g_lat_f);
    cudaGetSymbolAddress((void**)&kpe,    g_kpe);
    cudaGetSymbolAddress((void**)&qf,     g_qf);
    cudaGetSymbolAddress((void**)&kv16,   g_kv16);
    cudaGetSymbolAddress((void**)&Ofp,    g_Of);
    cudaGetSymbolAddress((void**)&Kcf,    g_Kc_f);
    cudaGetSymbolAddress((void**)&Vtf,    g_Vt_f);
    cudaGetSymbolAddress((void**)&wdTf,   g_wdTf);
    cudaGetSymbolAddress((void**)&wqbTf,  g_wqbTf);
    cudaGetSymbolAddress((void**)&wkvbTf, g_wkvbTf);
    cudaGetSymbolAddress((void**)&woTf,   g_woTf);

    const size_t nDP  = (size_t)T * DPW;
    const size_t nOut = (size_t)T * HID;

    dim3 blk(256);

    // ---- weight conversions ----
    conv_tr_f16_k<<<dim3(QLORA/32, HID/32), blk>>>(wq_a,  wdTf,                     HID, QLORA);
    conv_tr_f16_k<<<dim3(LATW/32,  HID/32), blk>>>(wkv_a, wdTf + (size_t)QLORA*HID, HID, LATW);
    conv_tr_f16_k<<<dim3(HDQ/32, QLORA/32), blk>>>(wq_b,  wqbTf,  QLORA, HDQ);
    conv_tr_f16_k<<<dim3(KVW/32,  DKV/32),  blk>>>(wkv_b, wkvbTf, DKV, KVW);
    conv_tr_f16_k<<<dim3(HID/32,  HDQ/32),  blk>>>(wo,    woTf,   HDQ, HID);
    conv_f16_k<<<2048, 256>>>(hidden, hidf, (long)T * HID);

    // ---- merged down projection, split-K=4 ----
    tgemm_1p<float><<<dim3((DPW + 127)/128, T/128, 4), blk, SMEM_1P>>>(hidf, wdTf,
        dpp, T, DPW, HID / 4, HID, HID, DPW, (long)nDP);

    // ---- rope(k_pe) + norms from 4 partials ----
    rope_kpe_4p_k<<<T, 32>>>(dpp, (long)nDP, pos, kpe);
    rmsnorm_4p_k<<<T, 256>>>(dpp,         (long)nDP, q_ln,  qlof, QLORA, DPW);
    rmsnorm_4p_k<<<T, 256>>>(dpp + QLORA, (long)nDP, kv_ln, latf, DKV,   DPW);

    // ---- fused up projections (qb scaled by 1/16) ----
    up_proj_k<<<dim3(64 + KVW/128, T/128), blk, SMEM_1P>>>(
        qlof, wqbTf, qf, latf, wkvbTf, kv16);

    // ---- q rope in place; K assembly; V transpose ----
    rope_q_inpl_k<<<T, 256>>>(qf, pos);
    build_K_h_k<<<T, 256>>>(kv16, kpe, Kcf);
    transpose_v_h_k<<<dim3(DV/32, T/32, NH), blk>>>(kv16, Vtf);

    // ---- fused flash attention ----
    flash_k<<<dim3(T/128, NH), blk, FA_SMEM>>>(qf, Kcf, Vtf, Ofp);

    // ---- final projection, split-K=4 + reduction ----
    tgemm_1p<float><<<dim3(HID/128, T/128, 4), blk, SMEM_1P>>>(Ofp, woTf,
        outp, T, HID, HDQ / 4, HDQ, HDQ, HID, (long)nOut);
    reduce4_k<<<1024, 256>>>(outp, outp + nOut, outp + 2 * nOut, outp + 3 * nOut,
        out, (long)(nOut / 4));
}

// round 16
// speedup vs baseline: 1.0143x; 1.0143x over previous
#include <cuda_runtime.h>
#include <cuda_fp16.h>
#include <math.h>
#include <stdint.h>

// ---------------- problem constants ----------------
constexpr int T    = 2048;
constexpr int HID  = 4096;
constexpr int NH   = 32;
constexpr int DQ   = 256;
constexpr int DN   = 192;
constexpr int DR   = 64;
constexpr int DV   = 256;
constexpr int DKV  = 512;
constexpr int QLORA= 2048;
constexpr int HDQ  = NH * DQ;        // 8192
constexpr int KVW  = NH * (DN + DV); // 14336
constexpr int LATW = DKV + DR;       // 576
constexpr int DPW  = QLORA + LATW;   // 2624

// ---------------- buffers ----------------
__device__ float  g_dp_part [2][(size_t)T * DPW];   // down-proj split-K=2 partials
__device__ float  g_out_part[4][(size_t)T * HID];   // wo split-K=4 partials
__device__ __half g_hid_f  [(size_t)T * HID];
__device__ __half g_qlo_f  [(size_t)T * QLORA];
__device__ __half g_lat_f  [(size_t)T * DKV];
__device__ __half g_kpe    [(size_t)T * DR];
__device__ __half g_qf     [(size_t)T * HDQ];       // q, pre-scaled by 1/16
__device__ __half g_kv16   [(size_t)T * KVW];
__device__ __half g_Of     [(size_t)T * HDQ];
__device__ __half g_Kc_f   [(size_t)T * HDQ];
__device__ __half g_Vt_f   [(size_t)NH * DV * T];
__device__ __half g_wdTf   [(size_t)DPW * HID];
__device__ __half g_wqbTf  [(size_t)HDQ * QLORA];
__device__ __half g_wkvbTf [(size_t)KVW * DKV];
__device__ __half g_woTf   [(size_t)HID * HDQ];

// ---------------- helpers ----------------
__device__ __forceinline__ void mma_f16(float* c, const uint32_t* a, const uint32_t* b) {
    asm volatile(
        "mma.sync.aligned.m16n8k16.row.col.f32.f16.f16.f32 "
        "{%0,%1,%2,%3}, {%4,%5,%6,%7}, {%8,%9}, {%0,%1,%2,%3};\n"
        : "+f"(c[0]), "+f"(c[1]), "+f"(c[2]), "+f"(c[3])
        : "r"(a[0]), "r"(a[1]), "r"(a[2]), "r"(a[3]), "r"(b[0]), "r"(b[1]));
}

__device__ __forceinline__ void ldsm4(uint32_t& r0, uint32_t& r1, uint32_t& r2, uint32_t& r3, uint32_t a) {
    asm volatile("ldmatrix.sync.aligned.m8n8.x4.shared.b16 {%0,%1,%2,%3}, [%4];"
        : "=r"(r0), "=r"(r1), "=r"(r2), "=r"(r3) : "r"(a));
}

__device__ __forceinline__ void cp16(uint32_t d, const void* s) {
    asm volatile("cp.async.cg.shared.global [%0], [%1], 16;" :: "r"(d), "l"(s));
}

constexpr int F_TILE  = 128 * 80;
constexpr int P_STAGE = 2 * F_TILE;
constexpr int SMEM_1P = 2 * P_STAGE;     // 40960

// ============================================================================
// 1-pass fp16 GEMM with optional split-K (blockIdx.z) and epilogue scale.
// ============================================================================
template <typename OutT>
__global__ __launch_bounds__(256, 2) void tgemm_1p(
    const __half* __restrict__ Ah, const __half* __restrict__ Bh,
    OutT* __restrict__ C,
    int M, int N, int K, int lda, int ldb, int ldc, long sC, float oscale)
{
    const int bx = blockIdx.x, by = blockIdx.y;
    Ah += (long)blockIdx.z * K;
    Bh += (long)blockIdx.z * K;
    C  += (long)blockIdx.z * sC;

    extern __shared__ char smem[];
    const uint32_t sb = (uint32_t)__cvta_generic_to_shared(smem);

    const int tid = threadIdx.x, lane = tid & 31, warp = tid >> 5;
    const int wm = warp & 1, wn = warp >> 1;
    const int g = lane >> 2, t4 = lane & 3;
    const int r0 = tid >> 2, c4 = tid & 3;
    const int Nm1 = N - 1;

    const int lr  = (lane & 7) + ((lane >> 3) & 1) * 8;
    const int lkb = (lane >> 4) * 16;
    const uint32_t aBase = sb + (uint32_t)((wm * 64 + lr) * 80 + lkb);
    const uint32_t bBase = sb + (uint32_t)(F_TILE + (wn * 32 + lr) * 80 + lkb);

    float acc[4][4][4] = {};
    const int nchunks = K / 32;

    auto load_chunk = [&](int k0, uint32_t st) {
        #pragma unroll
        for (int c = 0; c < 2; c++) {
            int row = r0 + c * 64;
            uint32_t ds = sb + st + (uint32_t)(row * 80 + c4 * 16);
            long aoff = (long)(by * 128 + row) * lda + k0 + c4 * 8;
            cp16(ds, Ah + aoff);
            int nr = bx * 128 + row; if (nr > Nm1) nr = Nm1;
            long boff = (long)nr * ldb + k0 + c4 * 8;
            cp16(ds + F_TILE, Bh + boff);
        }
    };

    load_chunk(0, 0);
    asm volatile("cp.async.commit_group;");

    for (int i = 0; i < nchunks; i++) {
        if (i + 1 < nchunks)
            load_chunk((i + 1) * 32, (uint32_t)(((i + 1) & 1) * P_STAGE));
        asm volatile("cp.async.commit_group;");
        asm volatile("cp.async.wait_group 1;");
        __syncthreads();

        const uint32_t sof = (uint32_t)((i & 1) * P_STAGE);
        #pragma unroll
        for (int ks = 0; ks < 2; ks++) {
            uint32_t bh[4][2];
            #pragma unroll
            for (int p = 0; p < 2; p++) {
                uint32_t ad = bBase + sof + (uint32_t)(p * 16 * 80 + ks * 32);
                uint32_t x0, x1, x2, x3;
                ldsm4(x0, x1, x2, x3, ad);
                bh[2*p][0] = x0; bh[2*p+1][0] = x1; bh[2*p][1] = x2; bh[2*p+1][1] = x3;
            }
            #pragma unroll
            for (int mt = 0; mt < 4; mt++) {
                uint32_t ah[4];
                uint32_t ad = aBase + sof + (uint32_t)(mt * 16 * 80 + ks * 32);
                ldsm4(ah[0], ah[1], ah[2], ah[3], ad);
                #pragma unroll
                for (int nt = 0; nt < 4; nt++)
                    mma_f16(acc[mt][nt], ah, bh[nt]);
            }
        }
        __syncthreads();
    }

    #pragma unroll
    for (int mt = 0; mt < 4; mt++) {
        int r = by * 128 + wm * 64 + mt * 16 + g;
        #pragma unroll
        for (int nt = 0; nt < 4; nt++) {
            int c = bx * 128 + wn * 32 + nt * 8 + 2 * t4;
            if (c < N) {
                if (sizeof(OutT) == 4) {
                    float* Cf = (float*)C;
                    *(float2*)&Cf[(long)r * ldc + c] =
                        make_float2(acc[mt][nt][0] * oscale, acc[mt][nt][1] * oscale);
                    *(float2*)&Cf[(long)(r + 8) * ldc + c] =
                        make_float2(acc[mt][nt][2] * oscale, acc[mt][nt][3] * oscale);
                } else {
                    __half* Ch = (__half*)C;
                    *(__half2*)&Ch[(long)r * ldc + c] =
                        __floats2half2_rn(acc[mt][nt][0] * oscale, acc[mt][nt][1] * oscale);
                    *(__half2*)&Ch[(long)(r + 8) * ldc + c] =
                        __floats2half2_rn(acc[mt][nt][2] * oscale, acc[mt][nt][3] * oscale);
                }
            }
        }
    }
}

// ============================================================================
// Fused flash attention, fp16 1-term, Q smem-resident, Q pre-scaled.
// ============================================================================
constexpr int QPL  = 10240;
constexpr int KOFF = 8 * QPL;
constexpr int VPL  = 34816;
constexpr int VOFF = KOFF + 2 * QPL;
constexpr int FA_SMEM = VOFF + 2 * VPL;  // 172032

__global__ __launch_bounds__(256, 1) void flash_k(
    const __half* __restrict__ Qf, const __half* __restrict__ Kf,
    const __half* __restrict__ Vf, __half* __restrict__ Of)
{
    const int qi = gridDim.x - 1 - blockIdx.x;
    const int h  = blockIdx.y;

    extern __shared__ char smem[];
    const uint32_t sb = (uint32_t)__cvta_generic_to_shared(smem);

    const int tid = threadIdx.x, lane = tid & 31, w = tid >> 5;
    const int g = lane >> 2, t4 = lane & 3;
    const int lr  = (lane & 7) + ((lane >> 3) & 1) * 8;
    const int lkb = (lane >> 4) * 16;

    #pragma unroll
    for (int p = 0; p < 16; p++) {
        int id = tid + p * 256;
        int chunk = id >> 9, wi = id & 511;
        int row = wi >> 2, cc = wi & 3;
        uint32_t dst = sb + (uint32_t)(chunk * QPL + row * 80 + cc * 16);
        size_t qo = (size_t)(qi * 128 + row) * HDQ + h * DQ + chunk * 32 + cc * 8;
        cp16(dst, Qf + qo);
    }
    asm volatile("cp.async.commit_group;");

    float oacc[32][4];
    #pragma unroll
    for (int i = 0; i < 32; i++)
        #pragma unroll
        for (int c = 0; c < 4; c++) oacc[i][c] = 0.f;
    float m0 = -1e30f, m1 = -1e30f, l0 = 0.f, l1 = 0.f;

    for (int j = 0; j <= qi; j++) {
        float sacc[16][4] = {};

        auto load_kc = [&](int i, uint32_t st) {
            const int d = i * 32;
            #pragma unroll
            for (int p = 0; p < 2; p++) {
                int id = tid + p * 256;
                int row = id >> 2, cc = id & 3;
                uint32_t dst = sb + st + (uint32_t)(row * 80 + cc * 16);
                size_t ko = (size_t)(j * 128 + row) * HDQ + h * DQ + d + cc * 8;
                cp16(dst, Kf + ko);
            }
        };

        load_kc(0, KOFF);
        asm volatile("cp.async.commit_group;");
        load_kc(1, KOFF + QPL);
        asm volatile("cp.async.commit_group;");

        #pragma unroll
        for (int dvc = 0; dvc < 2; dvc++) {
            #pragma unroll
            for (int p = 0; p < 4; p++) {
                int id = tid + p * 256;
                int row = id >> 3, cc = id & 7;
                uint32_t dst = sb + (uint32_t)(VOFF + dvc * VPL + row * 272 + cc * 32);
                size_t vo = (size_t)h * DV * T + (size_t)(dvc * 128 + row) * T + j * 128 + cc * 16;
                cp16(dst,      Vf + vo);
                cp16(dst + 16, Vf + vo + 8);
            }
        }
        asm volatile("cp.async.commit_group;");

        for (int i = 0; i < 8; i++) {
            asm volatile("cp.async.wait_group 1;");
            __syncthreads();
            const uint32_t st = (uint32_t)(KOFF + (i & 1) * QPL);
            const uint32_t qBase = sb + (uint32_t)(i * QPL + (w * 16 + lr) * 80 + lkb);
            #pragma unroll
            for (int ks = 0; ks < 2; ks++) {
                uint32_t ah[4];
                ldsm4(ah[0], ah[1], ah[2], ah[3], qBase + ks * 32);
                #pragma unroll
                for (int p = 0; p < 8; p++) {
                    uint32_t bh[2][2], x0, x1, x2, x3;
                    uint32_t bd = sb + st + (uint32_t)((p * 16 + lr) * 80 + lkb + ks * 32);
                    ldsm4(x0, x1, x2, x3, bd);
                    bh[0][0] = x0; bh[1][0] = x1; bh[0][1] = x2; bh[1][1] = x3;
                    #pragma unroll
                    for (int q2 = 0; q2 < 2; q2++)
                        mma_f16(sacc[p * 2 + q2], ah, bh[q2]);
                }
            }
            __syncthreads();
            if (i + 2 < 8) load_kc(i + 2, st);
            asm volatile("cp.async.commit_group;");
        }
        asm volatile("cp.async.wait_group 0;");

        // ---------------- softmax (Q pre-scaled) ----------------
        if (j == qi) {
            const int rr0 = w * 16 + g, rr1 = rr0 + 8;
            #pragma unroll
            for (int nt = 0; nt < 16; nt++) {
                int col = nt * 8 + 2 * t4;
                if (col     > rr0) sacc[nt][0] = -1e30f;
                if (col + 1 > rr0) sacc[nt][1] = -1e30f;
                if (col     > rr1) sacc[nt][2] = -1e30f;
                if (col + 1 > rr1) sacc[nt][3] = -1e30f;
            }
        }

        float tm0 = -1e30f, tm1 = -1e30f;
        #pragma unroll
        for (int nt = 0; nt < 16; nt++) {
            tm0 = fmaxf(tm0, fmaxf(sacc[nt][0], sacc[nt][1]));
            tm1 = fmaxf(tm1, fmaxf(sacc[nt][2], sacc[nt][3]));
        }
        tm0 = fmaxf(tm0, __shfl_xor_sync(0xffffffffu, tm0, 1));
        tm0 = fmaxf(tm0, __shfl_xor_sync(0xffffffffu, tm0, 2));
        tm1 = fmaxf(tm1, __shfl_xor_sync(0xffffffffu, tm1, 1));
        tm1 = fmaxf(tm1, __shfl_xor_sync(0xffffffffu, tm1, 2));

        float nm0 = fmaxf(m0, tm0), nm1 = fmaxf(m1, tm1);
        float a0 = expf(m0 - nm0), a1 = expf(m1 - nm1);
        m0 = nm0; m1 = nm1;

        float s0 = 0.f, s1 = 0.f;
        #pragma unroll
        for (int nt = 0; nt < 16; nt++) {
            sacc[nt][0] = expf(sacc[nt][0] - m0); s0 += sacc[nt][0];
            sacc[nt][1] = expf(sacc[nt][1] - m0); s0 += sacc[nt][1];
            sacc[nt][2] = expf(sacc[nt][2] - m1); s1 += sacc[nt][2];
            sacc[nt][3] = expf(sacc[nt][3] - m1); s1 += sacc[nt][3];
        }
        s0 += __shfl_xor_sync(0xffffffffu, s0, 1);
        s0 += __shfl_xor_sync(0xffffffffu, s0, 2);
        s1 += __shfl_xor_sync(0xffffffffu, s1, 1);
        s1 += __shfl_xor_sync(0xffffffffu, s1, 2);
        l0 = l0 * a0 + s0;
        l1 = l1 * a1 + s1;

        #pragma unroll
        for (int i = 0; i < 32; i++) {
            oacc[i][0] *= a0; oacc[i][1] *= a0;
            oacc[i][2] *= a1; oacc[i][3] *= a1;
        }

        uint32_t Pf[8][4];
        #pragma unroll
        for (int ks = 0; ks < 8; ks++) {
            #pragma unroll
            for (int hf = 0; hf < 2; hf++) {
                const float* c = sacc[2 * ks + hf];
                __half2 v01 = __floats2half2_rn(c[0], c[1]);
                __half2 v23 = __floats2half2_rn(c[2], c[3]);
                Pf[ks][hf * 2]     = *(uint32_t*)&v01;
                Pf[ks][hf * 2 + 1] = *(uint32_t*)&v23;
            }
        }

        __syncthreads();
        #pragma unroll
        for (int dvc = 0; dvc < 2; dvc++) {
            #pragma unroll
            for (int ks = 0; ks < 8; ks++) {
                #pragma unroll
                for (int p = 0; p < 8; p++) {
                    uint32_t vh[2][2], x0, x1, x2, x3;
                    uint32_t bd = sb + (uint32_t)(VOFF + dvc * VPL + (p * 16 + lr) * 272 + lkb + ks * 32);
                    ldsm4(x0, x1, x2, x3, bd);
                    vh[0][0] = x0; vh[1][0] = x1; vh[0][1] = x2; vh[1][1] = x3;
                    #pragma unroll
                    for (int q2 = 0; q2 < 2; q2++)
                        mma_f16(oacc[dvc * 16 + p * 2 + q2], Pf[ks], vh[q2]);
                }
            }
        }
        __syncthreads();
    }

    const float i0 = 1.f / l0, i1 = 1.f / l1;
    const int r0 = qi * 128 + w * 16 + g;
    __half* o0 = Of + (size_t)r0 * HDQ + h * DV;
    __half* o1 = o0 + (size_t)8 * HDQ;
    #pragma unroll
    for (int nt = 0; nt < 32; nt++) {
        int c = nt * 8 + 2 * t4;
        __half2 v0 = __floats2half2_rn(oacc[nt][0] * i0, oacc[nt][1] * i0);
        __half2 v1 = __floats2half2_rn(oacc[nt][2] * i1, oacc[nt][3] * i1);
        *(__half2*)&o0[c] = v0;
        *(__half2*)&o1[c] = v1;
    }
}

// ---------------- fp32 -> fp16 ----------------
__global__ void conv_f16_k(const float* __restrict__ x, __half* __restrict__ h, long n)
{
    long i = (long)blockIdx.x * blockDim.x + threadIdx.x;
    long stride = (long)gridDim.x * blockDim.x;
    for (; i < n; i += stride) h[i] = __float2half_rn(x[i]);
}

// ---------------- fp32 [R,C] -> fp16 transposed [C,R] ----------------
__global__ void conv_tr_f16_k(const float* __restrict__ x, __half* __restrict__ h, int R, int C)
{
    __shared__ float tile[32][33];
    const int c0 = blockIdx.x * 32, rr0 = blockIdx.y * 32;
    const int tx = threadIdx.x & 31, ty = threadIdx.x >> 5;
    #pragma unroll
    for (int i = 0; i < 4; i++) {
        int r = rr0 + ty + i * 8;
        tile[ty + i * 8][tx] = x[(long)r * C + c0 + tx];
    }
    __syncthreads();
    #pragma unroll
    for (int i = 0; i < 4; i++) {
        int c = c0 + ty + i * 8;
        long o = (long)c * R + rr0 + tx;
        h[o] = __float2half_rn(tile[tx][ty + i * 8]);
    }
}

// ---------------- RMSNorm from 2 fp32 partials -> fp16 ----------------
__global__ void rmsnorm_2p_k(const float* __restrict__ p0, const float* __restrict__ p1,
                             const float* __restrict__ w, __half* __restrict__ o,
                             int N, int ldin)
{
    long rb = (long)blockIdx.x * ldin;
    __shared__ float red[8];
    __shared__ float bc;
    const int lane = threadIdx.x & 31, wid = threadIdx.x >> 5;

    float s = 0.f;
    for (int j = threadIdx.x; j < N; j += blockDim.x) {
        float v = p0[rb + j] + p1[rb + j];
        s += v * v;
    }
    #pragma unroll
    for (int of = 16; of; of >>= 1) s += __shfl_xor_sync(0xffffffffu, s, of);
    if (lane == 0) red[wid] = s;
    __syncthreads();
    if (threadIdx.x == 0) {
        float v = 0.f;
        for (int wI = 0; wI < 8; wI++) v += red[wI];
        bc = rsqrtf(v / N + 1e-6f);
    }
    __syncthreads();
    float r = bc;
    long ob = (long)blockIdx.x * N;
    for (int j = threadIdx.x; j < N; j += blockDim.x) {
        float v = p0[rb + j] + p1[rb + j];
        o[ob + j] = __float2half_rn(v * r * w[j]);
    }
}

// ---------------- rope k_pe from 2 fp32 partials -> fp16 kpe ----------------
__global__ void rope_kpe_2p_k(const float* __restrict__ p0, const float* __restrict__ p1,
                              const int* __restrict__ pos, __half* __restrict__ kpe)
{
    const int tt = blockIdx.x, i = threadIdx.x;
    double inv = pow(10000.0, -(double)i / 32.0);
    double sd, cd;
    sincos((double)pos[tt] * inv, &sd, &cd);
    float c = (float)cd, s = (float)sd;
    long rb = (long)tt * DPW + QLORA + DKV;
    float x1 = p0[rb + i]      + p1[rb + i];
    float x2 = p0[rb + i + 32] + p1[rb + i + 32];
    kpe[(long)tt * DR + i]      = __float2half_rn(x1 * c - x2 * s);
    kpe[(long)tt * DR + i + 32] = __float2half_rn(x2 * c + x1 * s);
}

// ---------------- rope q in-place ----------------
__global__ void rope_q_inpl_k(__half* __restrict__ q, const int* __restrict__ pos)
{
    const int tt = blockIdx.x;
    const int i = threadIdx.x & 31, wg = threadIdx.x >> 5;
    double inv = pow(10000.0, -(double)i / 32.0);
    double sd, cd;
    sincos((double)pos[tt] * inv, &sd, &cd);
    float c = (float)cd, s = (float)sd;
    for (int h = wg; h < NH; h += 8) {
        __half* p = q + (size_t)tt * HDQ + h * DQ + DN;
        float x1 = __half2float(p[i]), x2 = __half2float(p[i + 32]);
        p[i]      = __float2half_rn(x1 * c - x2 * s);
        p[i + 32] = __float2half_rn(x2 * c + x1 * s);
    }
}

// ---------------- K assembly ----------------
__global__ void build_K_h_k(const __half* __restrict__ kv, const __half* __restrict__ kpe,
                            __half* __restrict__ Kc)
{
    const int tt = blockIdx.x;
    long ob = (long)tt * HDQ;
    for (int x = threadIdx.x; x < HDQ; x += blockDim.x) {
        int hd = x >> 8, d = x & 255;
        __half v = (d < DN) ? kv[(size_t)tt * KVW + hd * (DN + DV) + d]
                            : kpe[(long)tt * DR + (d - DN)];
        Kc[ob + x] = v;
    }
}

// ---------------- V transpose per head -> [h][DV][T] ----------------
__global__ void transpose_v_h_k(const __half* __restrict__ kv, __half* __restrict__ h)
{
    __shared__ __half tile[32][34];
    const int d0 = blockIdx.x * 32, t0 = blockIdx.y * 32, hd = blockIdx.z;
    const int tx = threadIdx.x & 31, ty = threadIdx.x >> 5;
    #pragma unroll
    for (int i = 0; i < 4; i++) {
        int tr = t0 + ty + i * 8;
        tile[ty + i * 8][tx] = kv[(size_t)tr * KVW + hd * (DN + DV) + DN + d0 + tx];
    }
    __syncthreads();
    #pragma unroll
    for (int i = 0; i < 4; i++) {
        int d = d0 + ty + i * 8;
        long o = (long)hd * DV * T + (long)d * T + t0 + tx;
        h[o] = tile[tx][ty + i * 8];
    }
}

// ---------------- 4-way fp32 reduction ----------------
__global__ void reduce4_k(const float* __restrict__ p0, const float* __restrict__ p1,
                          const float* __restrict__ p2, const float* __restrict__ p3,
                          float* __restrict__ o, long n4)
{
    long i = (long)blockIdx.x * blockDim.x + threadIdx.x;
    long stride = (long)gridDim.x * blockDim.x;
    for (; i < n4; i += stride) {
        float4 a = ((const float4*)p0)[i];
        float4 b = ((const float4*)p1)[i];
        float4 c = ((const float4*)p2)[i];
        float4 d = ((const float4*)p3)[i];
        ((float4*)o)[i] = make_float4(a.x + b.x + c.x + d.x, a.y + b.y + c.y + d.y,
                                      a.z + b.z + c.z + d.z, a.w + b.w + c.w + d.w);
    }
}

// ---------------- launch ----------------
extern "C" void kernel_launch(void* const* d_in, const int* in_sizes, int n_in,
                              void* d_out, int out_size)
{
    (void)in_sizes; (void)n_in; (void)out_size;
    const float* hidden = (const float*)d_in[0];
    const int*   pos    = (const int*)  d_in[1];
    const float* wq_a   = (const float*)d_in[2];
    const float* q_ln   = (const float*)d_in[3];
    const float* wq_b   = (const float*)d_in[4];
    const float* wkv_a  = (const float*)d_in[5];
    const float* kv_ln  = (const float*)d_in[6];
    const float* wkv_b  = (const float*)d_in[7];
    const float* wo     = (const float*)d_in[8];
    float* out = (float*)d_out;

    cudaFuncSetAttribute(tgemm_1p<__half>, cudaFuncAttributeMaxDynamicSharedMemorySize, SMEM_1P);
    cudaFuncSetAttribute(tgemm_1p<float>,  cudaFuncAttributeMaxDynamicSharedMemorySize, SMEM_1P);
    cudaFuncSetAttribute(flash_k,          cudaFuncAttributeMaxDynamicSharedMemorySize, FA_SMEM);

    float *dpp, *outp;
    cudaGetSymbolAddress((void**)&dpp,  g_dp_part);
    cudaGetSymbolAddress((void**)&outp, g_out_part);

    __half *hidf, *qlof, *latf, *kpe, *qf, *kv16, *Ofp, *Kcf, *Vtf,
           *wdTf, *wqbTf, *wkvbTf, *woTf;
    cudaGetSymbolAddress((void**)&hidf,   g_hid_f);
    cudaGetSymbolAddress((void**)&qlof,   g_qlo_f);
    cudaGetSymbolAddress((void**)&latf,   g_lat_f);
    cudaGetSymbolAddress((void**)&kpe,    g_kpe);
    cudaGetSymbolAddress((void**)&qf,     g_qf);
    cudaGetSymbolAddress((void**)&kv16,   g_kv16);
    cudaGetSymbolAddress((void**)&Ofp,    g_Of);
    cudaGetSymbolAddress((void**)&Kcf,    g_Kc_f);
    cudaGetSymbolAddress((void**)&Vtf,    g_Vt_f);
    cudaGetSymbolAddress((void**)&wdTf,   g_wdTf);
    cudaGetSymbolAddress((void**)&wqbTf,  g_wqbTf);
    cudaGetSymbolAddress((void**)&wkvbTf, g_wkvbTf);
    cudaGetSymbolAddress((void**)&woTf,   g_woTf);

    const size_t nDP  = (size_t)T * DPW;
    const size_t nOut = (size_t)T * HID;

    dim3 blk(256);

    // ---- weight conversions ----
    conv_tr_f16_k<<<dim3(QLORA/32, HID/32), blk>>>(wq_a,  wdTf,                     HID, QLORA);
    conv_tr_f16_k<<<dim3(LATW/32,  HID/32), blk>>>(wkv_a, wdTf + (size_t)QLORA*HID, HID, LATW);
    conv_tr_f16_k<<<dim3(HDQ/32, QLORA/32), blk>>>(wq_b,  wqbTf,  QLORA, HDQ);
    conv_tr_f16_k<<<dim3(KVW/32,  DKV/32),  blk>>>(wkv_b, wkvbTf, DKV, KVW);
    conv_tr_f16_k<<<dim3(HID/32,  HDQ/32),  blk>>>(wo,    woTf,   HDQ, HID);
    conv_f16_k<<<2048, 256>>>(hidden, hidf, (long)T * HID);

    // ---- merged down projection, split-K=2 (R14 proven) ----
    tgemm_1p<float><<<dim3((DPW + 127)/128, T/128, 2), blk, SMEM_1P>>>(hidf, wdTf,
        dpp, T, DPW, HID / 2, HID, HID, DPW, (long)nDP, 1.f);

    // ---- rope(k_pe) + norms from 2 partials ----
    rope_kpe_2p_k<<<T, 32>>>(dpp, dpp + nDP, pos, kpe);
    rmsnorm_2p_k<<<T, 256>>>(dpp,         dpp + nDP,         q_ln,  qlof, QLORA, DPW);
    rmsnorm_2p_k<<<T, 256>>>(dpp + QLORA, dpp + nDP + QLORA, kv_ln, latf, DKV,   DPW);

    // ---- up projections (separate launches; qb epilogue folds 1/16) ----
    tgemm_1p<__half><<<dim3(HDQ/128, T/128), blk, SMEM_1P>>>(qlof, wqbTf,
        qf, T, HDQ, QLORA, QLORA, QLORA, HDQ, 0, 0.0625f);
    tgemm_1p<__half><<<dim3(KVW/128, T/128), blk, SMEM_1P>>>(latf, wkvbTf,
        kv16, T, KVW, DKV, DKV, DKV, KVW, 0, 1.f);

    // ---- q rope in place; K assembly; V transpose ----
    rope_q_inpl_k<<<T, 256>>>(qf, pos);
    build_K_h_k<<<T, 256>>>(kv16, kpe, Kcf);
    transpose_v_h_k<<<dim3(DV/32, T/32, NH), blk>>>(kv16, Vtf);

    // ---- fused flash attention ----
    flash_k<<<dim3(T/128, NH), blk, FA_SMEM>>>(qf, Kcf, Vtf, Ofp);

    // ---- final projection, split-K=4 + reduction ----
    tgemm_1p<float><<<dim3(HID/128, T/128, 4), blk, SMEM_1P>>>(Ofp, woTf,
        outp, T, HID, HDQ / 4, HDQ, HDQ, HID, (long)nOut, 1.f);
    reduce4_k<<<1024, 256>>>(outp, outp + nOut, outp + 2 * nOut, outp + 3 * nOut,
        out, (long)(nOut / 4));
}

// round 17
// speedup vs baseline: 1.0167x; 1.0024x over previous
#include <cuda_runtime.h>
#include <cuda_fp16.h>
#include <math.h>
#include <stdint.h>

// ---------------- problem constants ----------------
constexpr int T    = 2048;
constexpr int HID  = 4096;
constexpr int NH   = 32;
constexpr int DQ   = 256;
constexpr int DN   = 192;
constexpr int DR   = 64;
constexpr int DV   = 256;
constexpr int DKV  = 512;
constexpr int QLORA= 2048;
constexpr int HDQ  = NH * DQ;        // 8192
constexpr int KVW  = NH * (DN + DV); // 14336
constexpr int LATW = DKV + DR;       // 576
constexpr int DPW  = QLORA + LATW;   // 2624

// ---------------- buffers ----------------
__device__ float  g_dp_part [2][(size_t)T * DPW];
__device__ float  g_out_part[4][(size_t)T * HID];
__device__ __half g_hid_f  [(size_t)T * HID];
__device__ __half g_qlo_f  [(size_t)T * QLORA];
__device__ __half g_lat_f  [(size_t)T * DKV];
__device__ __half g_kpe    [(size_t)T * DR];
__device__ __half g_qf     [(size_t)T * HDQ];       // q, pre-scaled by 1/16
__device__ __half g_kv16   [(size_t)T * KVW];
__device__ __half g_Of     [(size_t)T * HDQ];
__device__ __half g_Kc_f   [(size_t)T * HDQ];
__device__ __half g_Vt_f   [(size_t)NH * DV * T];
__device__ __half g_wdTf   [(size_t)DPW * HID];
__device__ __half g_wqbTf  [(size_t)HDQ * QLORA];
__device__ __half g_wkvbTf [(size_t)KVW * DKV];
__device__ __half g_woTf   [(size_t)HID * HDQ];

// ---------------- helpers ----------------
__device__ __forceinline__ void mma_f16(float* c, const uint32_t* a, const uint32_t* b) {
    asm volatile(
        "mma.sync.aligned.m16n8k16.row.col.f32.f16.f16.f32 "
        "{%0,%1,%2,%3}, {%4,%5,%6,%7}, {%8,%9}, {%0,%1,%2,%3};\n"
        : "+f"(c[0]), "+f"(c[1]), "+f"(c[2]), "+f"(c[3])
        : "r"(a[0]), "r"(a[1]), "r"(a[2]), "r"(a[3]), "r"(b[0]), "r"(b[1]));
}

__device__ __forceinline__ void ldsm4(uint32_t& r0, uint32_t& r1, uint32_t& r2, uint32_t& r3, uint32_t a) {
    asm volatile("ldmatrix.sync.aligned.m8n8.x4.shared.b16 {%0,%1,%2,%3}, [%4];"
        : "=r"(r0), "=r"(r1), "=r"(r2), "=r"(r3) : "r"(a));
}

__device__ __forceinline__ void cp16(uint32_t d, const void* s) {
    asm volatile("cp.async.cg.shared.global [%0], [%1], 16;" :: "r"(d), "l"(s));
}

constexpr int F_TILE  = 128 * 80;
constexpr int P_STAGE = 2 * F_TILE;
constexpr int SMEM_1P = 2 * P_STAGE;     // 40960

// ============================================================================
// 1-pass fp16 GEMM with optional split-K (blockIdx.z) and epilogue scale.
// ============================================================================
template <typename OutT>
__global__ __launch_bounds__(256, 2) void tgemm_1p(
    const __half* __restrict__ Ah, const __half* __restrict__ Bh,
    OutT* __restrict__ C,
    int M, int N, int K, int lda, int ldb, int ldc, long sC, float oscale)
{
    const int bx = blockIdx.x, by = blockIdx.y;
    Ah += (long)blockIdx.z * K;
    Bh += (long)blockIdx.z * K;
    C  += (long)blockIdx.z * sC;

    extern __shared__ char smem[];
    const uint32_t sb = (uint32_t)__cvta_generic_to_shared(smem);

    const int tid = threadIdx.x, lane = tid & 31, warp = tid >> 5;
    const int wm = warp & 1, wn = warp >> 1;
    const int g = lane >> 2, t4 = lane & 3;
    const int r0 = tid >> 2, c4 = tid & 3;
    const int Nm1 = N - 1;

    const int lr  = (lane & 7) + ((lane >> 3) & 1) * 8;
    const int lkb = (lane >> 4) * 16;
    const uint32_t aBase = sb + (uint32_t)((wm * 64 + lr) * 80 + lkb);
    const uint32_t bBase = sb + (uint32_t)(F_TILE + (wn * 32 + lr) * 80 + lkb);

    float acc[4][4][4] = {};
    const int nchunks = K / 32;

    auto load_chunk = [&](int k0, uint32_t st) {
        #pragma unroll
        for (int c = 0; c < 2; c++) {
            int row = r0 + c * 64;
            uint32_t ds = sb + st + (uint32_t)(row * 80 + c4 * 16);
            long aoff = (long)(by * 128 + row) * lda + k0 + c4 * 8;
            cp16(ds, Ah + aoff);
            int nr = bx * 128 + row; if (nr > Nm1) nr = Nm1;
            long boff = (long)nr * ldb + k0 + c4 * 8;
            cp16(ds + F_TILE, Bh + boff);
        }
    };

    load_chunk(0, 0);
    asm volatile("cp.async.commit_group;");

    for (int i = 0; i < nchunks; i++) {
        if (i + 1 < nchunks)
            load_chunk((i + 1) * 32, (uint32_t)(((i + 1) & 1) * P_STAGE));
        asm volatile("cp.async.commit_group;");
        asm volatile("cp.async.wait_group 1;");
        __syncthreads();

        const uint32_t sof = (uint32_t)((i & 1) * P_STAGE);
        #pragma unroll
        for (int ks = 0; ks < 2; ks++) {
            uint32_t bh[4][2];
            #pragma unroll
            for (int p = 0; p < 2; p++) {
                uint32_t ad = bBase + sof + (uint32_t)(p * 16 * 80 + ks * 32);
                uint32_t x0, x1, x2, x3;
                ldsm4(x0, x1, x2, x3, ad);
                bh[2*p][0] = x0; bh[2*p+1][0] = x1; bh[2*p][1] = x2; bh[2*p+1][1] = x3;
            }
            #pragma unroll
            for (int mt = 0; mt < 4; mt++) {
                uint32_t ah[4];
                uint32_t ad = aBase + sof + (uint32_t)(mt * 16 * 80 + ks * 32);
                ldsm4(ah[0], ah[1], ah[2], ah[3], ad);
                #pragma unroll
                for (int nt = 0; nt < 4; nt++)
                    mma_f16(acc[mt][nt], ah, bh[nt]);
            }
        }
        __syncthreads();
    }

    #pragma unroll
    for (int mt = 0; mt < 4; mt++) {
        int r = by * 128 + wm * 64 + mt * 16 + g;
        #pragma unroll
        for (int nt = 0; nt < 4; nt++) {
            int c = bx * 128 + wn * 32 + nt * 8 + 2 * t4;
            if (c < N) {
                if (sizeof(OutT) == 4) {
                    float* Cf = (float*)C;
                    *(float2*)&Cf[(long)r * ldc + c] =
                        make_float2(acc[mt][nt][0] * oscale, acc[mt][nt][1] * oscale);
                    *(float2*)&Cf[(long)(r + 8) * ldc + c] =
                        make_float2(acc[mt][nt][2] * oscale, acc[mt][nt][3] * oscale);
                } else {
                    __half* Ch = (__half*)C;
                    *(__half2*)&Ch[(long)r * ldc + c] =
                        __floats2half2_rn(acc[mt][nt][0] * oscale, acc[mt][nt][1] * oscale);
                    *(__half2*)&Ch[(long)(r + 8) * ldc + c] =
                        __floats2half2_rn(acc[mt][nt][2] * oscale, acc[mt][nt][3] * oscale);
                }
            }
        }
    }
}

// ============================================================================
// Fused flash attention, fp16 1-term, Q smem-resident, Q pre-scaled.
// Next-tile K chunks 0-1 prefetched during softmax/PV (inter-tile overlap).
// ============================================================================
constexpr int QPL  = 10240;
constexpr int KOFF = 8 * QPL;
constexpr int VPL  = 34816;
constexpr int VOFF = KOFF + 2 * QPL;
constexpr int FA_SMEM = VOFF + 2 * VPL;  // 172032

__global__ __launch_bounds__(256, 1) void flash_k(
    const __half* __restrict__ Qf, const __half* __restrict__ Kf,
    const __half* __restrict__ Vf, __half* __restrict__ Of)
{
    const int qi = gridDim.x - 1 - blockIdx.x;
    const int h  = blockIdx.y;

    extern __shared__ char smem[];
    const uint32_t sb = (uint32_t)__cvta_generic_to_shared(smem);

    const int tid = threadIdx.x, lane = tid & 31, w = tid >> 5;
    const int g = lane >> 2, t4 = lane & 3;
    const int lr  = (lane & 7) + ((lane >> 3) & 1) * 8;
    const int lkb = (lane >> 4) * 16;

    // K chunk loader for tile jj, d-chunk i, into stage st
    auto load_kc = [&](int jj, int i, uint32_t st) {
        const int d = i * 32;
        #pragma unroll
        for (int p = 0; p < 2; p++) {
            int id = tid + p * 256;
            int row = id >> 2, cc = id & 3;
            uint32_t dst = sb + st + (uint32_t)(row * 80 + cc * 16);
            size_t ko = (size_t)(jj * 128 + row) * HDQ + h * DQ + d + cc * 8;
            cp16(dst, Kf + ko);
        }
    };

    // ---- Q resident load + tile-0 K prefetch ----
    #pragma unroll
    for (int p = 0; p < 16; p++) {
        int id = tid + p * 256;
        int chunk = id >> 9, wi = id & 511;
        int row = wi >> 2, cc = wi & 3;
        uint32_t dst = sb + (uint32_t)(chunk * QPL + row * 80 + cc * 16);
        size_t qo = (size_t)(qi * 128 + row) * HDQ + h * DQ + chunk * 32 + cc * 8;
        cp16(dst, Qf + qo);
    }
    asm volatile("cp.async.commit_group;");
    load_kc(0, 0, KOFF);
    asm volatile("cp.async.commit_group;");
    load_kc(0, 1, KOFF + QPL);
    asm volatile("cp.async.commit_group;");

    float oacc[32][4];
    #pragma unroll
    for (int i = 0; i < 32; i++)
        #pragma unroll
        for (int c = 0; c < 4; c++) oacc[i][c] = 0.f;
    float m0 = -1e30f, m1 = -1e30f, l0 = 0.f, l1 = 0.f;

    for (int j = 0; j <= qi; j++) {
        float sacc[16][4] = {};

        // V prefetch for this tile (K0/K1 already in flight from previous phase)
        #pragma unroll
        for (int dvc = 0; dvc < 2; dvc++) {
            #pragma unroll
            for (int p = 0; p < 4; p++) {
                int id = tid + p * 256;
                int row = id >> 3, cc = id & 7;
                uint32_t dst = sb + (uint32_t)(VOFF + dvc * VPL + row * 272 + cc * 32);
                size_t vo = (size_t)h * DV * T + (size_t)(dvc * 128 + row) * T + j * 128 + cc * 16;
                cp16(dst,      Vf + vo);
                cp16(dst + 16, Vf + vo + 8);
            }
        }
        asm volatile("cp.async.commit_group;");

        for (int i = 0; i < 8; i++) {
            asm volatile("cp.async.wait_group 1;");
            __syncthreads();
            const uint32_t st = (uint32_t)(KOFF + (i & 1) * QPL);
            const uint32_t qBase = sb + (uint32_t)(i * QPL + (w * 16 + lr) * 80 + lkb);
            #pragma unroll
            for (int ks = 0; ks < 2; ks++) {
                uint32_t ah[4];
                ldsm4(ah[0], ah[1], ah[2], ah[3], qBase + ks * 32);
                #pragma unroll
                for (int p = 0; p < 8; p++) {
                    uint32_t bh[2][2], x0, x1, x2, x3;
                    uint32_t bd = sb + st + (uint32_t)((p * 16 + lr) * 80 + lkb + ks * 32);
                    ldsm4(x0, x1, x2, x3, bd);
                    bh[0][0] = x0; bh[1][0] = x1; bh[0][1] = x2; bh[1][1] = x3;
                    #pragma unroll
                    for (int q2 = 0; q2 < 2; q2++)
                        mma_f16(sacc[p * 2 + q2], ah, bh[q2]);
                }
            }
            __syncthreads();
            if (i + 2 < 8) load_kc(j, i + 2, st);
            asm volatile("cp.async.commit_group;");
        }
        asm volatile("cp.async.wait_group 0;");

        // ---- prefetch next tile's K chunks 0-1 (overlaps softmax + PV) ----
        // safe: all warps passed the last QK __syncthreads (K smem reads done)
        if (j < qi) {
            load_kc(j + 1, 0, KOFF);
            asm volatile("cp.async.commit_group;");
            load_kc(j + 1, 1, KOFF + QPL);
            asm volatile("cp.async.commit_group;");
        }

        // ---------------- softmax (Q pre-scaled) ----------------
        if (j == qi) {
            const int rr0 = w * 16 + g, rr1 = rr0 + 8;
            #pragma unroll
            for (int nt = 0; nt < 16; nt++) {
                int col = nt * 8 + 2 * t4;
                if (col     > rr0) sacc[nt][0] = -1e30f;
                if (col + 1 > rr0) sacc[nt][1] = -1e30f;
                if (col     > rr1) sacc[nt][2] = -1e30f;
                if (col + 1 > rr1) sacc[nt][3] = -1e30f;
            }
        }

        float tm0 = -1e30f, tm1 = -1e30f;
        #pragma unroll
        for (int nt = 0; nt < 16; nt++) {
            tm0 = fmaxf(tm0, fmaxf(sacc[nt][0], sacc[nt][1]));
            tm1 = fmaxf(tm1, fmaxf(sacc[nt][2], sacc[nt][3]));
        }
        tm0 = fmaxf(tm0, __shfl_xor_sync(0xffffffffu, tm0, 1));
        tm0 = fmaxf(tm0, __shfl_xor_sync(0xffffffffu, tm0, 2));
        tm1 = fmaxf(tm1, __shfl_xor_sync(0xffffffffu, tm1, 1));
        tm1 = fmaxf(tm1, __shfl_xor_sync(0xffffffffu, tm1, 2));

        float nm0 = fmaxf(m0, tm0), nm1 = fmaxf(m1, tm1);
        float a0 = expf(m0 - nm0), a1 = expf(m1 - nm1);
        m0 = nm0; m1 = nm1;

        float s0 = 0.f, s1 = 0.f;
        #pragma unroll
        for (int nt = 0; nt < 16; nt++) {
            sacc[nt][0] = expf(sacc[nt][0] - m0); s0 += sacc[nt][0];
            sacc[nt][1] = expf(sacc[nt][1] - m0); s0 += sacc[nt][1];
            sacc[nt][2] = expf(sacc[nt][2] - m1); s1 += sacc[nt][2];
            sacc[nt][3] = expf(sacc[nt][3] - m1); s1 += sacc[nt][3];
        }
        s0 += __shfl_xor_sync(0xffffffffu, s0, 1);
        s0 += __shfl_xor_sync(0xffffffffu, s0, 2);
        s1 += __shfl_xor_sync(0xffffffffu, s1, 1);
        s1 += __shfl_xor_sync(0xffffffffu, s1, 2);
        l0 = l0 * a0 + s0;
        l1 = l1 * a1 + s1;

        #pragma unroll
        for (int i = 0; i < 32; i++) {
            oacc[i][0] *= a0; oacc[i][1] *= a0;
            oacc[i][2] *= a1; oacc[i][3] *= a1;
        }

        uint32_t Pf[8][4];
        #pragma unroll
        for (int ks = 0; ks < 8; ks++) {
            #pragma unroll
            for (int hf = 0; hf < 2; hf++) {
                const float* c = sacc[2 * ks + hf];
                __half2 v01 = __floats2half2_rn(c[0], c[1]);
                __half2 v23 = __floats2half2_rn(c[2], c[3]);
                Pf[ks][hf * 2]     = *(uint32_t*)&v01;
                Pf[ks][hf * 2 + 1] = *(uint32_t*)&v23;
            }
        }

        __syncthreads();
        #pragma unroll
        for (int dvc = 0; dvc < 2; dvc++) {
            #pragma unroll
            for (int ks = 0; ks < 8; ks++) {
                #pragma unroll
                for (int p = 0; p < 8; p++) {
                    uint32_t vh[2][2], x0, x1, x2, x3;
                    uint32_t bd = sb + (uint32_t)(VOFF + dvc * VPL + (p * 16 + lr) * 272 + lkb + ks * 32);
                    ldsm4(x0, x1, x2, x3, bd);
                    vh[0][0] = x0; vh[1][0] = x1; vh[0][1] = x2; vh[1][1] = x3;
                    #pragma unroll
                    for (int q2 = 0; q2 < 2; q2++)
                        mma_f16(oacc[dvc * 16 + p * 2 + q2], Pf[ks], vh[q2]);
                }
            }
        }
        __syncthreads();
    }

    const float i0 = 1.f / l0, i1 = 1.f / l1;
    const int r0 = qi * 128 + w * 16 + g;
    __half* o0 = Of + (size_t)r0 * HDQ + h * DV;
    __half* o1 = o0 + (size_t)8 * HDQ;
    #pragma unroll
    for (int nt = 0; nt < 32; nt++) {
        int c = nt * 8 + 2 * t4;
        __half2 v0 = __floats2half2_rn(oacc[nt][0] * i0, oacc[nt][1] * i0);
        __half2 v1 = __floats2half2_rn(oacc[nt][2] * i1, oacc[nt][3] * i1);
        *(__half2*)&o0[c] = v0;
        *(__half2*)&o1[c] = v1;
    }
}

// ---------------- fp32 -> fp16 ----------------
__global__ void conv_f16_k(const float* __restrict__ x, __half* __restrict__ h, long n)
{
    long i = (long)blockIdx.x * blockDim.x + threadIdx.x;
    long stride = (long)gridDim.x * blockDim.x;
    for (; i < n; i += stride) h[i] = __float2half_rn(x[i]);
}

// ---------------- fp32 [R,C] -> fp16 transposed [C,R] ----------------
__global__ void conv_tr_f16_k(const float* __restrict__ x, __half* __restrict__ h, int R, int C)
{
    __shared__ float tile[32][33];
    const int c0 = blockIdx.x * 32, rr0 = blockIdx.y * 32;
    const int tx = threadIdx.x & 31, ty = threadIdx.x >> 5;
    #pragma unroll
    for (int i = 0; i < 4; i++) {
        int r = rr0 + ty + i * 8;
        tile[ty + i * 8][tx] = x[(long)r * C + c0 + tx];
    }
    __syncthreads();
    #pragma unroll
    for (int i = 0; i < 4; i++) {
        int c = c0 + ty + i * 8;
        long o = (long)c * R + rr0 + tx;
        h[o] = __float2half_rn(tile[tx][ty + i * 8]);
    }
}

// ---------------- RMSNorm from 2 fp32 partials -> fp16 ----------------
__global__ void rmsnorm_2p_k(const float* __restrict__ p0, const float* __restrict__ p1,
                             const float* __restrict__ w, __half* __restrict__ o,
                             int N, int ldin)
{
    long rb = (long)blockIdx.x * ldin;
    __shared__ float red[8];
    __shared__ float bc;
    const int lane = threadIdx.x & 31, wid = threadIdx.x >> 5;

    float s = 0.f;
    for (int j = threadIdx.x; j < N; j += blockDim.x) {
        float v = p0[rb + j] + p1[rb + j];
        s += v * v;
    }
    #pragma unroll
    for (int of = 16; of; of >>= 1) s += __shfl_xor_sync(0xffffffffu, s, of);
    if (lane == 0) red[wid] = s;
    __syncthreads();
    if (threadIdx.x == 0) {
        float v = 0.f;
        for (int wI = 0; wI < 8; wI++) v += red[wI];
        bc = rsqrtf(v / N + 1e-6f);
    }
    __syncthreads();
    float r = bc;
    long ob = (long)blockIdx.x * N;
    for (int j = threadIdx.x; j < N; j += blockDim.x) {
        float v = p0[rb + j] + p1[rb + j];
        o[ob + j] = __float2half_rn(v * r * w[j]);
    }
}

// ---------------- rope k_pe from 2 fp32 partials -> fp16 kpe ----------------
__global__ void rope_kpe_2p_k(const float* __restrict__ p0, const float* __restrict__ p1,
                              const int* __restrict__ pos, __half* __restrict__ kpe)
{
    const int tt = blockIdx.x, i = threadIdx.x;
    double inv = pow(10000.0, -(double)i / 32.0);
    double sd, cd;
    sincos((double)pos[tt] * inv, &sd, &cd);
    float c = (float)cd, s = (float)sd;
    long rb = (long)tt * DPW + QLORA + DKV;
    float x1 = p0[rb + i]      + p1[rb + i];
    float x2 = p0[rb + i + 32] + p1[rb + i + 32];
    kpe[(long)tt * DR + i]      = __float2half_rn(x1 * c - x2 * s);
    kpe[(long)tt * DR + i + 32] = __float2half_rn(x2 * c + x1 * s);
}

// ---------------- rope q in-place ----------------
__global__ void rope_q_inpl_k(__half* __restrict__ q, const int* __restrict__ pos)
{
    const int tt = blockIdx.x;
    const int i = threadIdx.x & 31, wg = threadIdx.x >> 5;
    double inv = pow(10000.0, -(double)i / 32.0);
    double sd, cd;
    sincos((double)pos[tt] * inv, &sd, &cd);
    float c = (float)cd, s = (float)sd;
    for (int h = wg; h < NH; h += 8) {
        __half* p = q + (size_t)tt * HDQ + h * DQ + DN;
        float x1 = __half2float(p[i]), x2 = __half2float(p[i + 32]);
        p[i]      = __float2half_rn(x1 * c - x2 * s);
        p[i + 32] = __float2half_rn(x2 * c + x1 * s);
    }
}

// ---------------- K assembly ----------------
__global__ void build_K_h_k(const __half* __restrict__ kv, const __half* __restrict__ kpe,
                            __half* __restrict__ Kc)
{
    const int tt = blockIdx.x;
    long ob = (long)tt * HDQ;
    for (int x = threadIdx.x; x < HDQ; x += blockDim.x) {
        int hd = x >> 8, d = x & 255;
        __half v = (d < DN) ? kv[(size_t)tt * KVW + hd * (DN + DV) + d]
                            : kpe[(long)tt * DR + (d - DN)];
        Kc[ob + x] = v;
    }
}

// ---------------- V transpose per head -> [h][DV][T] ----------------
__global__ void transpose_v_h_k(const __half* __restrict__ kv, __half* __restrict__ h)
{
    __shared__ __half tile[32][34];
    const int d0 = blockIdx.x * 32, t0 = blockIdx.y * 32, hd = blockIdx.z;
    const int tx = threadIdx.x & 31, ty = threadIdx.x >> 5;
    #pragma unroll
    for (int i = 0; i < 4; i++) {
        int tr = t0 + ty + i * 8;
        tile[ty + i * 8][tx] = kv[(size_t)tr * KVW + hd * (DN + DV) + DN + d0 + tx];
    }
    __syncthreads();
    #pragma unroll
    for (int i = 0; i < 4; i++) {
        int d = d0 + ty + i * 8;
        long o = (long)hd * DV * T + (long)d * T + t0 + tx;
        h[o] = tile[tx][ty + i * 8];
    }
}

// ---------------- 4-way fp32 reduction ----------------
__global__ void reduce4_k(const float* __restrict__ p0, const float* __restrict__ p1,
                          const float* __restrict__ p2, const float* __restrict__ p3,
                          float* __restrict__ o, long n4)
{
    long i = (long)blockIdx.x * blockDim.x + threadIdx.x;
    long stride = (long)gridDim.x * blockDim.x;
    for (; i < n4; i += stride) {
        float4 a = ((const float4*)p0)[i];
        float4 b = ((const float4*)p1)[i];
        float4 c = ((const float4*)p2)[i];
        float4 d = ((const float4*)p3)[i];
        ((float4*)o)[i] = make_float4(a.x + b.x + c.x + d.x, a.y + b.y + c.y + d.y,
                                      a.z + b.z + c.z + d.z, a.w + b.w + c.w + d.w);
    }
}

// ---------------- launch ----------------
extern "C" void kernel_launch(void* const* d_in, const int* in_sizes, int n_in,
                              void* d_out, int out_size)
{
    (void)in_sizes; (void)n_in; (void)out_size;
    const float* hidden = (const float*)d_in[0];
    const int*   pos    = (const int*)  d_in[1];
    const float* wq_a   = (const float*)d_in[2];
    const float* q_ln   = (const float*)d_in[3];
    const float* wq_b   = (const float*)d_in[4];
    const float* wkv_a  = (const float*)d_in[5];
    const float* kv_ln  = (const float*)d_in[6];
    const float* wkv_b  = (const float*)d_in[7];
    const float* wo     = (const float*)d_in[8];
    float* out = (float*)d_out;

    cudaFuncSetAttribute(tgemm_1p<__half>, cudaFuncAttributeMaxDynamicSharedMemorySize, SMEM_1P);
    cudaFuncSetAttribute(tgemm_1p<float>,  cudaFuncAttributeMaxDynamicSharedMemorySize, SMEM_1P);
    cudaFuncSetAttribute(flash_k,          cudaFuncAttributeMaxDynamicSharedMemorySize, FA_SMEM);

    float *dpp, *outp;
    cudaGetSymbolAddress((void**)&dpp,  g_dp_part);
    cudaGetSymbolAddress((void**)&outp, g_out_part);

    __half *hidf, *qlof, *latf, *kpe, *qf, *kv16, *Ofp, *Kcf, *Vtf,
           *wdTf, *wqbTf, *wkvbTf, *woTf;
    cudaGetSymbolAddress((void**)&hidf,   g_hid_f);
    cudaGetSymbolAddress((void**)&qlof,   g_qlo_f);
    cudaGetSymbolAddress((void**)&latf,   g_lat_f);
    cudaGetSymbolAddress((void**)&kpe,    g_kpe);
    cudaGetSymbolAddress((void**)&qf,     g_qf);
    cudaGetSymbolAddress((void**)&kv16,   g_kv16);
    cudaGetSymbolAddress((void**)&Ofp,    g_Of);
    cudaGetSymbolAddress((void**)&Kcf,    g_Kc_f);
    cudaGetSymbolAddress((void**)&Vtf,    g_Vt_f);
    cudaGetSymbolAddress((void**)&wdTf,   g_wdTf);
    cudaGetSymbolAddress((void**)&wqbTf,  g_wqbTf);
    cudaGetSymbolAddress((void**)&wkvbTf, g_wkvbTf);
    cudaGetSymbolAddress((void**)&woTf,   g_woTf);

    const size_t nDP  = (size_t)T * DPW;
    const size_t nOut = (size_t)T * HID;

    dim3 blk(256);

    // ---- weight conversions ----
    conv_tr_f16_k<<<dim3(QLORA/32, HID/32), blk>>>(wq_a,  wdTf,                     HID, QLORA);
    conv_tr_f16_k<<<dim3(LATW/32,  HID/32), blk>>>(wkv_a, wdTf + (size_t)QLORA*HID, HID, LATW);
    conv_tr_f16_k<<<dim3(HDQ/32, QLORA/32), blk>>>(wq_b,  wqbTf,  QLORA, HDQ);
    conv_tr_f16_k<<<dim3(KVW/32,  DKV/32),  blk>>>(wkv_b, wkvbTf, DKV, KVW);
    conv_tr_f16_k<<<dim3(HID/32,  HDQ/32),  blk>>>(wo,    woTf,   HDQ, HID);
    conv_f16_k<<<2048, 256>>>(hidden, hidf, (long)T * HID);

    // ---- merged down projection, split-K=2 ----
    tgemm_1p<float><<<dim3((DPW + 127)/128, T/128, 2), blk, SMEM_1P>>>(hidf, wdTf,
        dpp, T, DPW, HID / 2, HID, HID, DPW, (long)nDP, 1.f);

    // ---- rope(k_pe) + norms from 2 partials ----
    rope_kpe_2p_k<<<T, 32>>>(dpp, dpp + nDP, pos, kpe);
    rmsnorm_2p_k<<<T, 256>>>(dpp,         dpp + nDP,         q_ln,  qlof, QLORA, DPW);
    rmsnorm_2p_k<<<T, 256>>>(dpp + QLORA, dpp + nDP + QLORA, kv_ln, latf, DKV,   DPW);

    // ---- up projections (qb epilogue folds 1/16) ----
    tgemm_1p<__half><<<dim3(HDQ/128, T/128), blk, SMEM_1P>>>(qlof, wqbTf,
        qf, T, HDQ, QLORA, QLORA, QLORA, HDQ, 0, 0.0625f);
    tgemm_1p<__half><<<dim3(KVW/128, T/128), blk, SMEM_1P>>>(latf, wkvbTf,
        kv16, T, KVW, DKV, DKV, DKV, KVW, 0, 1.f);

    // ---- q rope in place; K assembly; V transpose ----
    rope_q_inpl_k<<<T, 256>>>(qf, pos);
    build_K_h_k<<<T, 256>>>(kv16, kpe, Kcf);
    transpose_v_h_k<<<dim3(DV/32, T/32, NH), blk>>>(kv16, Vtf);

    // ---- fused flash attention (inter-tile K prefetch) ----
    flash_k<<<dim3(T/128, NH), blk, FA_SMEM>>>(qf, Kcf, Vtf, Ofp);

    // ---- final projection, split-K=4 + reduction ----
    tgemm_1p<float><<<dim3(HID/128, T/128, 4), blk, SMEM_1P>>>(Ofp, woTf,
        outp, T, HID, HDQ / 4, HDQ, HDQ, HID, (long)nOut, 1.f);
    reduce4_k<<<1024, 256>>>(outp, outp + nOut, outp + 2 * nOut, outp + 3 * nOut,
        out, (long)(nOut / 4));
}